// round 7
// baseline (speedup 1.0000x reference)
#include <cuda_runtime.h>
#include <cuda_bf16.h>
#include <cstdint>
#include <cstddef>

// ============================================================================
// proj[b,c] = sum_{i,j} t[b,i] * W[c, i*512+j] * f[b,j]   (B=2048, F=512, C=64)
// out = relu(relu(proj + bp) @ W1^T + b1) @ W2^T + b2
//
// tf32 mma.sync.m16n8k8 warp GEMM (tcgen05 unavailable at sm_103 target).
//   conv:  t,W -> tf32 bits in EXACT mma fragment order. convW does a coalesced
//          smem transpose (float4 loads, conflict-free gather, 256B warp writes).
//   gemm:  512 thr / 16 warps, warp tile 64x32, CTA tile 256(m)x128(n), K=512,
//          K-chunk 16, 4-stage cp.async pipeline (96KB).  4 warps/SMSP.
//          Epilogue: partial[b,c] = sum_j P[b,j]*f[b,j] (16 deterministic slices)
//   mlp:   sum 16 slices, bias, relu, 64->32->1.
// ============================================================================

// g_T  [btile(8)][kc8(64)][mt(16)][lane(32)][4]     (4 MB)
// g_W  [c(64)][jt(4)][kc8(64)][nt(16)][lane(32)][2] (64 MB)
__device__ uint32_t g_T[8 * 64 * 16 * 32 * 4];
__device__ uint32_t g_W[64 * 4 * 64 * 16 * 32 * 2];
__device__ float    g_partial[16 * 2048 * 64];   // 8 MB

// ---------------- helpers ----------------
__device__ __forceinline__ uint32_t f2tf32(float x) {
    uint32_t r;
    asm("cvt.rna.tf32.f32 %0, %1;" : "=r"(r) : "f"(x));
    return r;
}
__device__ __forceinline__ void cp16(uint32_t dst_smem, const void* src) {
    asm volatile("cp.async.cg.shared.global [%0], [%1], 16;" :: "r"(dst_smem), "l"(src));
}
__device__ __forceinline__ void cp_commit() {
    asm volatile("cp.async.commit_group;" ::: "memory");
}
__device__ __forceinline__ void cp_wait2() {
    asm volatile("cp.async.wait_group 2;" ::: "memory");
}
__device__ __forceinline__ void mma_tf32(float* d, const uint32_t* a, const uint32_t* b) {
    asm volatile(
        "mma.sync.aligned.m16n8k8.row.col.f32.tf32.tf32.f32 "
        "{%0,%1,%2,%3},{%4,%5,%6,%7},{%8,%9},{%0,%1,%2,%3};"
        : "+f"(d[0]), "+f"(d[1]), "+f"(d[2]), "+f"(d[3])
        : "r"(a[0]), "r"(a[1]), "r"(a[2]), "r"(a[3]), "r"(b[0]), "r"(b[1]));
}

// ---------------- conv ----------------
// blocks [0, 2048): convW via smem transpose.
//   block = (c, jt, ktile): W rows k in [ktile*64,+64), cols n in [jt*128,+128).
//   Load coalesced float4, cvt->tf32, smem gather to fragment order, write 256B/warp.
// blocks [2048, 3072): convT (A fragments), original scheme.
__global__ void conv_kernel(const float* __restrict__ t, const float* __restrict__ W) {
    if (blockIdx.x < 2048) {
        __shared__ uint32_t ws[64 * 132];
        int b = blockIdx.x;
        int c = b >> 5, jt = (b >> 3) & 3, ktile = b & 7;
        int tid = threadIdx.x, lane = tid & 31, warp = tid >> 5;

        // load 64(k) x 128(n) tile, coalesced float4 per thread
        const float* src = W + (size_t)c * 262144 + (size_t)(ktile * 64) * 512 + jt * 128;
#pragma unroll
        for (int r = 0; r < 8; r++) {
            int k = r * 8 + warp;
            float4 v = *(const float4*)&src[(size_t)k * 512 + lane * 4];
            uint32_t* d = &ws[k * 132 + lane * 4];
            d[0] = f2tf32(v.x); d[1] = f2tf32(v.y); d[2] = f2tf32(v.z); d[3] = f2tf32(v.w);
        }
        __syncthreads();

        // gather fragments: warp w handles chunk kc2 = w; b0=(k=lane&3, n=lane>>2)
        uint32_t* dst = g_W + ((size_t)((c * 4 + jt) * 64 + ktile * 8 + warp) * 4096 + lane * 8) / 4;
        int r0 = (warp * 8 + (lane & 3)) * 132 + (lane >> 2);
#pragma unroll
        for (int nt = 0; nt < 16; nt++) {
            uint32_t v0 = ws[r0 + nt * 8];
            uint32_t v1 = ws[r0 + 4 * 132 + nt * 8];
            *(uint2*)&dst[nt * 64] = make_uint2(v0, v1);
        }
    } else {
        int gid = (blockIdx.x - 2048) * 256 + threadIdx.x;
        int lane  = gid & 31;
        int mt    = (gid >> 5) & 15;
        int kc    = (gid >> 9) & 63;
        int btile = gid >> 15;
        int row0 = btile * 256 + mt * 16 + (lane >> 2);
        int col0 = kc * 8 + (lane & 3);
        uint32_t v[4];
#pragma unroll
        for (int r = 0; r < 4; r++) {
            int row = row0 + 8 * (r & 1);
            int col = col0 + 4 * (r >> 1);
            v[r] = f2tf32(t[(size_t)row * 512 + col]);
        }
        *(uint4*)&g_T[(size_t)gid * 4] = make_uint4(v[0], v[1], v[2], v[3]);
    }
}

// ---------------- GEMM + f-dot epilogue ----------------
// 512 threads / 16 warps: mw = warp&3 (64 m-rows), nw = warp>>2 (32 n-cols).
// Dynamic smem: 4 stages x 24576 B (A 16KB + B 8KB, frag-order, contiguous).
static constexpr uint32_t STAGE_SZ  = 24576;
static constexpr uint32_t SMEM_GEMM = 4 * STAGE_SZ;  // 98304

__global__ __launch_bounds__(512, 1) void gemm_kernel(const float* __restrict__ f_feat) {
    extern __shared__ __align__(16) unsigned char smem_dyn[];
    uint32_t* smem = (uint32_t*)smem_dyn;
    int tid = threadIdx.x;
    int lane = tid & 31, warp = tid >> 5;
    int mw = warp & 3, nw = warp >> 2;
    int btile = blockIdx.x, jt = blockIdx.y, c = blockIdx.z;

    const char* gA = (const char*)g_T + (size_t)btile * 64 * 8192;
    const char* gB = (const char*)g_W + (size_t)((c * 4 + jt) * 64) * 4096;
    uint32_t sbase = (uint32_t)__cvta_generic_to_shared(smem);

    // prime 3 stages (stage = A 16KB + B 8KB; 512 thr x 48B)
#pragma unroll
    for (int s = 0; s < 3; s++) {
        uint32_t d = sbase + s * STAGE_SZ;
        cp16(d + tid * 16,          gA + (size_t)s * 16384 + tid * 16);
        cp16(d + 8192 + tid * 16,   gA + (size_t)s * 16384 + 8192 + tid * 16);
        cp16(d + 16384 + tid * 16,  gB + (size_t)s * 8192 + tid * 16);
        cp_commit();
    }

    float acc[4][4][4];
#pragma unroll
    for (int mt = 0; mt < 4; mt++)
#pragma unroll
        for (int nt = 0; nt < 4; nt++)
#pragma unroll
            for (int q = 0; q < 4; q++) acc[mt][nt][q] = 0.f;

    for (int it = 0; it < 32; it++) {
        cp_wait2();
        __syncthreads();
        int s = it & 3;
        const uint32_t* sA = smem + s * (STAGE_SZ / 4);
        const uint32_t* sB = sA + 4096;

#pragma unroll
        for (int sub = 0; sub < 2; sub++) {
            const uint32_t* pA = sA + sub * 2048;
            const uint32_t* pB = sB + sub * 1024;
            uint32_t bfr[4][2];
#pragma unroll
            for (int nt = 0; nt < 4; nt++) {
                uint2 bb = *(const uint2*)&pB[((nw * 4 + nt) * 32 + lane) * 2];
                bfr[nt][0] = bb.x; bfr[nt][1] = bb.y;
            }
#pragma unroll
            for (int mt = 0; mt < 4; mt++) {
                uint4 aa = *(const uint4*)&pA[((mw * 4 + mt) * 32 + lane) * 4];
                uint32_t afr[4] = {aa.x, aa.y, aa.z, aa.w};
#pragma unroll
                for (int nt = 0; nt < 4; nt++)
                    mma_tf32(acc[mt][nt], afr, bfr[nt]);
            }
        }

        if (it < 29) {
            int kn = it + 3;
            uint32_t d = sbase + (kn & 3) * STAGE_SZ;
            cp16(d + tid * 16,         gA + (size_t)kn * 16384 + tid * 16);
            cp16(d + 8192 + tid * 16,  gA + (size_t)kn * 16384 + 8192 + tid * 16);
            cp16(d + 16384 + tid * 16, gB + (size_t)kn * 8192 + tid * 16);
        }
        cp_commit();   // empty group when it >= 29 keeps wait arithmetic uniform
    }

    // ---------------- epilogue: partial[b,c] = sum_j P[b,j] * f[b,j] ----------------
    float* fs = (float*)smem;   // 64 rows x 132 floats
    for (int p = 0; p < 4; p++) {
        __syncthreads();
        for (int i = tid; i < 64 * 32; i += 512) {
            int row = i >> 5, cg = i & 31;
            float4 v = *(const float4*)&f_feat[(size_t)(btile * 256 + p * 64 + row) * 512 + jt * 128 + cg * 4];
            *(float4*)&fs[row * 132 + cg * 4] = v;
        }
        __syncthreads();
        if (mw == p) {
#pragma unroll
            for (int mt = 0; mt < 4; mt++) {
#pragma unroll
                for (int h = 0; h < 2; h++) {
                    int fl = mt * 16 + (lane >> 2) + 8 * h;   // local row 0..63
                    float sum = 0.f;
#pragma unroll
                    for (int nt = 0; nt < 4; nt++) {
                        float2 fv = *(const float2*)&fs[fl * 132 + nw * 32 + nt * 8 + 2 * (lane & 3)];
                        sum = fmaf(acc[mt][nt][h * 2], fv.x, sum);
                        sum = fmaf(acc[mt][nt][h * 2 + 1], fv.y, sum);
                    }
                    sum += __shfl_xor_sync(0xffffffffu, sum, 1);
                    sum += __shfl_xor_sync(0xffffffffu, sum, 2);
                    if ((lane & 3) == 0) {
                        int bb = btile * 256 + p * 64 + fl;
                        g_partial[(size_t)(jt * 4 + nw) * 131072 + (size_t)bb * 64 + c] = sum;
                    }
                }
            }
        }
    }
}

// ---------------- MLP: sum 16 slices + bias + relu + 64->32->1 ----------------
__global__ void mlp_kernel(const float* __restrict__ b_proj, const float* __restrict__ W1,
                           const float* __restrict__ b1, const float* __restrict__ W2,
                           const float* __restrict__ b2, float* __restrict__ out) {
    __shared__ float sW1[2048], sb1[32], sW2[32], sbp[64];
    int tid = threadIdx.x;
    for (int i = tid; i < 2048; i += 32) sW1[i] = W1[i];
    if (tid < 32) { sb1[tid] = b1[tid]; sW2[tid] = W2[tid]; }
    for (int i = tid; i < 64; i += 32) sbp[i] = b_proj[i];
    __syncthreads();

    int b = blockIdx.x * 32 + tid;
    float h[64];
#pragma unroll
    for (int cg = 0; cg < 16; cg++) {
        float4 v = *(const float4*)&g_partial[(size_t)b * 64 + cg * 4];
#pragma unroll
        for (int s = 1; s < 16; s++) {
            float4 p = *(const float4*)&g_partial[(size_t)s * 131072 + (size_t)b * 64 + cg * 4];
            v.x += p.x; v.y += p.y; v.z += p.z; v.w += p.w;
        }
        h[cg * 4 + 0] = fmaxf(v.x + sbp[cg * 4 + 0], 0.f);
        h[cg * 4 + 1] = fmaxf(v.y + sbp[cg * 4 + 1], 0.f);
        h[cg * 4 + 2] = fmaxf(v.z + sbp[cg * 4 + 2], 0.f);
        h[cg * 4 + 3] = fmaxf(v.w + sbp[cg * 4 + 3], 0.f);
    }
    float logit = b2[0];
#pragma unroll
    for (int k = 0; k < 32; k++) {
        float a = sb1[k];
#pragma unroll
        for (int cc = 0; cc < 64; cc++)
            a = fmaf(h[cc], sW1[k * 64 + cc], a);
        logit = fmaf(fmaxf(a, 0.f), sW2[k], logit);
    }
    out[b] = logit;
}

// ---------------- launcher ----------------
extern "C" void kernel_launch(void* const* d_in, const int* in_sizes, int n_in,
                              void* d_out, int out_size) {
    const float* t_feat = (const float*)d_in[0];
    const float* f_feat = (const float*)d_in[1];
    const float* W_proj = (const float*)d_in[2];
    const float* b_proj = (const float*)d_in[3];
    const float* W1     = (const float*)d_in[4];
    const float* b1     = (const float*)d_in[5];
    const float* W2     = (const float*)d_in[6];
    const float* b2     = (const float*)d_in[7];
    float* out = (float*)d_out;

    cudaFuncSetAttribute(gemm_kernel, cudaFuncAttributeMaxDynamicSharedMemorySize, SMEM_GEMM);

    conv_kernel<<<3072, 256>>>(t_feat, W_proj);
    dim3 grid(8, 4, 64);   // (btile, jt, c) — btile fastest keeps W slice hot in L2
    gemm_kernel<<<grid, 512, SMEM_GEMM>>>(f_feat);
    mlp_kernel<<<64, 32>>>(b_proj, W1, b1, W2, b2, out);
}

// round 8
// speedup vs baseline: 1.5272x; 1.5272x over previous
#include <cuda_runtime.h>
#include <cuda_fp16.h>
#include <cstdint>
#include <cstddef>

// ============================================================================
// proj[b,c] = sum_{i,j} t[b,i] * W[c, i*512+j] * f[b,j]   (B=2048, F=512, C=64)
// out = relu(relu(proj + bp) @ W1^T + b1) @ W2^T + b2
//
// fp16 mma.sync.m16n8k16 warp GEMM (same 10-bit mantissa as tf32 -> same
// rel_err ~4e-4, but 2x FLOP/instruction on the legacy HMMA pipe).
//   conv:  t,W -> fp16 pairs in EXACT mma fragment order. convW: coalesced
//          smem transpose. convT: direct gather.
//   gemm:  256 thr / 8 warps, warp tile 64x64, CTA tile 256(m)x128(n), K=512,
//          K-chunk 32/stage, 4-stage cp.async pipeline (96KB).
//          Epilogue: partial[b,c] = sum_j P[b,j]*f[b,j] (8 deterministic slices)
//          Split into 4 launches over c so ncu lands on a gemm launch.
//   mlp:   sum 8 slices, bias, relu, 64->32->1.
// ============================================================================

// g_T [btile(8)][kc16(32)][mt(16)][lane(32)][4 u32]   (2 MB)
// g_W [c(64)][jt(4)][kc16(32)][nt(16)][lane(32)][2 u32] (33.5 MB)
__device__ uint32_t g_T[8 * 32 * 16 * 32 * 4];
__device__ uint32_t g_W[64 * 4 * 32 * 16 * 32 * 2];
__device__ float    g_partial[8 * 2048 * 64];

// ---------------- helpers ----------------
__device__ __forceinline__ uint32_t packh2(float lo, float hi) {
    __half2 h = __floats2half2_rn(lo, hi);   // lo -> .x (low half)
    return *(uint32_t*)&h;
}
__device__ __forceinline__ void cp16(uint32_t dst_smem, const void* src) {
    asm volatile("cp.async.cg.shared.global [%0], [%1], 16;" :: "r"(dst_smem), "l"(src));
}
__device__ __forceinline__ void cp_commit() {
    asm volatile("cp.async.commit_group;" ::: "memory");
}
__device__ __forceinline__ void cp_wait2() {
    asm volatile("cp.async.wait_group 2;" ::: "memory");
}
__device__ __forceinline__ void mma_f16(float* d, const uint32_t* a, const uint32_t* b) {
    asm volatile(
        "mma.sync.aligned.m16n8k16.row.col.f32.f16.f16.f32 "
        "{%0,%1,%2,%3},{%4,%5,%6,%7},{%8,%9},{%0,%1,%2,%3};"
        : "+f"(d[0]), "+f"(d[1]), "+f"(d[2]), "+f"(d[3])
        : "r"(a[0]), "r"(a[1]), "r"(a[2]), "r"(a[3]), "r"(b[0]), "r"(b[1]));
}

// ---------------- conv ----------------
// blocks [0, 2048): convW via smem transpose. block = (c, jt, ktile64).
// blocks [2048, 2560): convT direct fragment gather.
__global__ void conv_kernel(const float* __restrict__ t, const float* __restrict__ W) {
    if (blockIdx.x < 2048) {
        __shared__ float ws[64 * 132];
        int b = blockIdx.x;
        int c = b >> 5, jt = (b >> 3) & 3, ktile = b & 7;
        int tid = threadIdx.x, lane = tid & 31, warp = tid >> 5;

        // load 64(k) x 128(n) tile, coalesced float4
        const float* src = W + (size_t)c * 262144 + (size_t)(ktile * 64) * 512 + jt * 128;
#pragma unroll
        for (int r = 0; r < 8; r++) {
            int k = r * 8 + warp;
            float4 v = *(const float4*)&src[(size_t)k * 512 + lane * 4];
            float* d = &ws[k * 132 + lane * 4];
            d[0] = v.x; d[1] = v.y; d[2] = v.z; d[3] = v.w;
        }
        __syncthreads();

        // gather fp16 B fragments. pair p = warp*8+i: q = kc16-within-slab, nt.
        // frag thread 'lane': b0 = (k0, n),(k0+1, n); b1 = (k0+8, n),(k0+9, n)
        //   k0 = (lane&3)*2 + q*16 (local), n = nt*8 + lane>>2
#pragma unroll
        for (int i = 0; i < 8; i++) {
            int p = warp * 8 + i;
            int q = p >> 4, nt = p & 15;
            int k0 = q * 16 + (lane & 3) * 2;
            int n  = nt * 8 + (lane >> 2);
            uint32_t v0 = packh2(ws[k0 * 132 + n],       ws[(k0 + 1) * 132 + n]);
            uint32_t v1 = packh2(ws[(k0 + 8) * 132 + n], ws[(k0 + 9) * 132 + n]);
            size_t base = ((size_t)((c * 4 + jt) * 32 + ktile * 4 + q) * 16 + nt) * 64 + lane * 2;
            *(uint2*)&g_W[base] = make_uint2(v0, v1);
        }
    } else {
        // convT: A 16x16 frag. thread: a0=(r, k0,k0+1) a1=(r+8,.) a2=(r, k0+8..) a3=(r+8, k0+8..)
        int gid = (blockIdx.x - 2048) * 256 + threadIdx.x;   // 131072 total
        int lane  = gid & 31;
        int mt    = (gid >> 5) & 15;
        int kc    = (gid >> 9) & 31;
        int btile = gid >> 14;
        int row = btile * 256 + mt * 16 + (lane >> 2);
        int k0  = kc * 16 + (lane & 3) * 2;
        float2 p00 = *(const float2*)&t[(size_t)row * 512 + k0];
        float2 p10 = *(const float2*)&t[(size_t)(row + 8) * 512 + k0];
        float2 p01 = *(const float2*)&t[(size_t)row * 512 + k0 + 8];
        float2 p11 = *(const float2*)&t[(size_t)(row + 8) * 512 + k0 + 8];
        uint32_t a0 = packh2(p00.x, p00.y);
        uint32_t a1 = packh2(p10.x, p10.y);
        uint32_t a2 = packh2(p01.x, p01.y);
        uint32_t a3 = packh2(p11.x, p11.y);
        *(uint4*)&g_T[(size_t)gid * 4] = make_uint4(a0, a1, a2, a3);
    }
}

// ---------------- GEMM + f-dot epilogue ----------------
// 256 thr / 8 warps: mw=warp&3 (64 m-rows), nw=warp>>2 (64 n-cols = 8 nt).
// Stage = K32: A 16KB + B 8KB (frag-order, contiguous). 4 stages = 96KB.
static constexpr uint32_t STAGE_SZ  = 24576;
static constexpr uint32_t SMEM_GEMM = 4 * STAGE_SZ;

__global__ __launch_bounds__(256, 1) void gemm_kernel(const float* __restrict__ f_feat, int c0) {
    extern __shared__ __align__(16) unsigned char smem_dyn[];
    uint32_t* smem = (uint32_t*)smem_dyn;
    int tid = threadIdx.x;
    int lane = tid & 31, warp = tid >> 5;
    int mw = warp & 3, nw = warp >> 2;
    int btile = blockIdx.x, jt = blockIdx.y, c = c0 + blockIdx.z;

    const char* gA = (const char*)g_T + (size_t)btile * 32 * 8192;           // 256KB per btile
    const char* gB = (const char*)g_W + (size_t)((c * 4 + jt) * 32) * 4096;  // 128KB per (c,jt)
    uint32_t sbase = (uint32_t)__cvta_generic_to_shared(smem);

    // prime 3 stages (stage: A 16KB + B 8KB; 256 thr)
#pragma unroll
    for (int s = 0; s < 3; s++) {
        uint32_t d = sbase + s * STAGE_SZ;
#pragma unroll
        for (int q = 0; q < 4; q++)
            cp16(d + q * 4096 + tid * 16, gA + (size_t)s * 16384 + q * 4096 + tid * 16);
#pragma unroll
        for (int q = 0; q < 2; q++)
            cp16(d + 16384 + q * 4096 + tid * 16, gB + (size_t)s * 8192 + q * 4096 + tid * 16);
        cp_commit();
    }

    float acc[4][8][4];
#pragma unroll
    for (int mt = 0; mt < 4; mt++)
#pragma unroll
        for (int nt = 0; nt < 8; nt++)
#pragma unroll
            for (int q = 0; q < 4; q++) acc[mt][nt][q] = 0.f;

    for (int it = 0; it < 16; it++) {
        cp_wait2();
        __syncthreads();
        int s = it & 3;
        const uint32_t* sA = smem + s * (STAGE_SZ / 4);
        const uint32_t* sB = sA + 4096;

#pragma unroll
        for (int sub = 0; sub < 2; sub++) {
            const uint32_t* pA = sA + sub * 2048;
            const uint32_t* pB = sB + sub * 1024;
            uint32_t bfr[8][2];
#pragma unroll
            for (int nt = 0; nt < 8; nt++) {
                uint2 bb = *(const uint2*)&pB[((nw * 8 + nt) * 32 + lane) * 2];
                bfr[nt][0] = bb.x; bfr[nt][1] = bb.y;
            }
#pragma unroll
            for (int mt = 0; mt < 4; mt++) {
                uint4 aa = *(const uint4*)&pA[((mw * 4 + mt) * 32 + lane) * 4];
                uint32_t afr[4] = {aa.x, aa.y, aa.z, aa.w};
#pragma unroll
                for (int nt = 0; nt < 8; nt++)
                    mma_f16(acc[mt][nt], afr, bfr[nt]);
            }
        }

        if (it < 13) {
            int kn = it + 3;
            uint32_t d = sbase + (kn & 3) * STAGE_SZ;
#pragma unroll
            for (int q = 0; q < 4; q++)
                cp16(d + q * 4096 + tid * 16, gA + (size_t)kn * 16384 + q * 4096 + tid * 16);
#pragma unroll
            for (int q = 0; q < 2; q++)
                cp16(d + 16384 + q * 4096 + tid * 16, gB + (size_t)kn * 8192 + q * 4096 + tid * 16);
        }
        cp_commit();   // empty group when it >= 13 keeps wait arithmetic uniform
    }

    // ---------------- epilogue: partial[b,c] = sum_j P[b,j] * f[b,j] ----------------
    float* fs = (float*)smem;   // 64 rows x 132 floats
    for (int p = 0; p < 4; p++) {
        __syncthreads();
        for (int i = tid; i < 64 * 32; i += 256) {
            int row = i >> 5, cg = i & 31;
            float4 v = *(const float4*)&f_feat[(size_t)(btile * 256 + p * 64 + row) * 512 + jt * 128 + cg * 4];
            *(float4*)&fs[row * 132 + cg * 4] = v;
        }
        __syncthreads();
        if (mw == p) {
#pragma unroll
            for (int mt = 0; mt < 4; mt++) {
#pragma unroll
                for (int h = 0; h < 2; h++) {
                    int fl = mt * 16 + (lane >> 2) + 8 * h;   // local row 0..63
                    float sum = 0.f;
#pragma unroll
                    for (int nt = 0; nt < 8; nt++) {
                        float2 fv = *(const float2*)&fs[fl * 132 + nw * 64 + nt * 8 + 2 * (lane & 3)];
                        sum = fmaf(acc[mt][nt][h * 2], fv.x, sum);
                        sum = fmaf(acc[mt][nt][h * 2 + 1], fv.y, sum);
                    }
                    sum += __shfl_xor_sync(0xffffffffu, sum, 1);
                    sum += __shfl_xor_sync(0xffffffffu, sum, 2);
                    if ((lane & 3) == 0) {
                        int bb = btile * 256 + p * 64 + fl;
                        g_partial[(size_t)(jt * 2 + nw) * 131072 + (size_t)bb * 64 + c] = sum;
                    }
                }
            }
        }
    }
}

// ---------------- MLP: sum 8 slices + bias + relu + 64->32->1 ----------------
__global__ void mlp_kernel(const float* __restrict__ b_proj, const float* __restrict__ W1,
                           const float* __restrict__ b1, const float* __restrict__ W2,
                           const float* __restrict__ b2, float* __restrict__ out) {
    __shared__ float sW1[2048], sb1[32], sW2[32], sbp[64];
    int tid = threadIdx.x;
    for (int i = tid; i < 2048; i += 32) sW1[i] = W1[i];
    if (tid < 32) { sb1[tid] = b1[tid]; sW2[tid] = W2[tid]; }
    for (int i = tid; i < 64; i += 32) sbp[i] = b_proj[i];
    __syncthreads();

    int b = blockIdx.x * 32 + tid;
    float h[64];
#pragma unroll
    for (int cg = 0; cg < 16; cg++) {
        float4 v = *(const float4*)&g_partial[(size_t)b * 64 + cg * 4];
#pragma unroll
        for (int s = 1; s < 8; s++) {
            float4 p = *(const float4*)&g_partial[(size_t)s * 131072 + (size_t)b * 64 + cg * 4];
            v.x += p.x; v.y += p.y; v.z += p.z; v.w += p.w;
        }
        h[cg * 4 + 0] = fmaxf(v.x + sbp[cg * 4 + 0], 0.f);
        h[cg * 4 + 1] = fmaxf(v.y + sbp[cg * 4 + 1], 0.f);
        h[cg * 4 + 2] = fmaxf(v.z + sbp[cg * 4 + 2], 0.f);
        h[cg * 4 + 3] = fmaxf(v.w + sbp[cg * 4 + 3], 0.f);
    }
    float logit = b2[0];
#pragma unroll
    for (int k = 0; k < 32; k++) {
        float a = sb1[k];
#pragma unroll
        for (int cc = 0; cc < 64; cc++)
            a = fmaf(h[cc], sW1[k * 64 + cc], a);
        logit = fmaf(fmaxf(a, 0.f), sW2[k], logit);
    }
    out[b] = logit;
}

// ---------------- launcher ----------------
extern "C" void kernel_launch(void* const* d_in, const int* in_sizes, int n_in,
                              void* d_out, int out_size) {
    const float* t_feat = (const float*)d_in[0];
    const float* f_feat = (const float*)d_in[1];
    const float* W_proj = (const float*)d_in[2];
    const float* b_proj = (const float*)d_in[3];
    const float* W1     = (const float*)d_in[4];
    const float* b1     = (const float*)d_in[5];
    const float* W2     = (const float*)d_in[6];
    const float* b2     = (const float*)d_in[7];
    float* out = (float*)d_out;

    cudaFuncSetAttribute(gemm_kernel, cudaFuncAttributeMaxDynamicSharedMemorySize, SMEM_GEMM);

    conv_kernel<<<2560, 256>>>(t_feat, W_proj);
    // 4 gemm launches over c-groups: same total work, and ncu's fixed sample
    // index now lands on a gemm launch.
    for (int g = 0; g < 4; g++) {
        dim3 grid(8, 4, 16);
        gemm_kernel<<<grid, 256, SMEM_GEMM>>>(f_feat, g * 16);
    }
    mlp_kernel<<<64, 32>>>(b_proj, W1, b1, W2, b2, out);
}

// round 9
// speedup vs baseline: 1.6811x; 1.1008x over previous
#include <cuda_runtime.h>
#include <cuda_fp16.h>
#include <cstdint>
#include <cstddef>

// ============================================================================
// proj[b,c] = sum_{i,j} t[b,i] * W[c, i*512+j] * f[b,j]   (B=2048, F=512, C=64)
// out = relu(relu(proj + bp) @ W1^T + b1) @ W2^T + b2
//
// fp16 mma.sync.m16n8k16 (rt~8cyc/SMSP measured => gemm floor ~126us).
//   conv:  t,W -> fp16 pairs in EXACT mma fragment order.
//   gemm:  256 thr / 8 warps, warp 64x64, CTA 256(m)x128(n), K=512.
//          A: 4-stage cp.async (16KB/stage). B: DIRECT LDG.64 from L2
//          (fragment order in gmem), register-prefetched 1 k16-step ahead.
//          Smem/iter: 88KB -> 48KB, unstarving the tensor pipe.
//          ONE launch, grid (8,4,64) = 2048 CTAs (13.8 waves, no quantization).
//   mlp:   sum 8 deterministic slices, bias, relu, 64->32->1.
// ============================================================================

// g_T [btile(8)][kc16(32)][mt(16)][lane(32)][4 u32]     (2 MB)
// g_W [c(64)][jt(4)][kc16(32)][nt(16)][lane(32)][2 u32] (33.5 MB)
__device__ uint32_t g_T[8 * 32 * 16 * 32 * 4];
__device__ uint32_t g_W[64 * 4 * 32 * 16 * 32 * 2];
__device__ float    g_partial[8 * 2048 * 64];

// ---------------- helpers ----------------
__device__ __forceinline__ uint32_t packh2(float lo, float hi) {
    __half2 h = __floats2half2_rn(lo, hi);
    return *(uint32_t*)&h;
}
__device__ __forceinline__ void cp16(uint32_t dst_smem, const void* src) {
    asm volatile("cp.async.cg.shared.global [%0], [%1], 16;" :: "r"(dst_smem), "l"(src));
}
__device__ __forceinline__ void cp_commit() {
    asm volatile("cp.async.commit_group;" ::: "memory");
}
__device__ __forceinline__ void cp_wait2() {
    asm volatile("cp.async.wait_group 2;" ::: "memory");
}
__device__ __forceinline__ void mma_f16(float* d, const uint32_t* a, const uint32_t* b) {
    asm volatile(
        "mma.sync.aligned.m16n8k16.row.col.f32.f16.f16.f32 "
        "{%0,%1,%2,%3},{%4,%5,%6,%7},{%8,%9},{%0,%1,%2,%3};"
        : "+f"(d[0]), "+f"(d[1]), "+f"(d[2]), "+f"(d[3])
        : "r"(a[0]), "r"(a[1]), "r"(a[2]), "r"(a[3]), "r"(b[0]), "r"(b[1]));
}

// ---------------- conv (unchanged from R7: fragment-order fp16) ----------------
__global__ void conv_kernel(const float* __restrict__ t, const float* __restrict__ W) {
    if (blockIdx.x < 2048) {
        __shared__ float ws[64 * 132];
        int b = blockIdx.x;
        int c = b >> 5, jt = (b >> 3) & 3, ktile = b & 7;
        int tid = threadIdx.x, lane = tid & 31, warp = tid >> 5;

        const float* src = W + (size_t)c * 262144 + (size_t)(ktile * 64) * 512 + jt * 128;
#pragma unroll
        for (int r = 0; r < 8; r++) {
            int k = r * 8 + warp;
            float4 v = *(const float4*)&src[(size_t)k * 512 + lane * 4];
            float* d = &ws[k * 132 + lane * 4];
            d[0] = v.x; d[1] = v.y; d[2] = v.z; d[3] = v.w;
        }
        __syncthreads();

#pragma unroll
        for (int i = 0; i < 8; i++) {
            int p = warp * 8 + i;
            int q = p >> 4, nt = p & 15;
            int k0 = q * 16 + (lane & 3) * 2;
            int n  = nt * 8 + (lane >> 2);
            uint32_t v0 = packh2(ws[k0 * 132 + n],       ws[(k0 + 1) * 132 + n]);
            uint32_t v1 = packh2(ws[(k0 + 8) * 132 + n], ws[(k0 + 9) * 132 + n]);
            size_t base = ((size_t)((c * 4 + jt) * 32 + ktile * 4 + q) * 16 + nt) * 64 + lane * 2;
            *(uint2*)&g_W[base] = make_uint2(v0, v1);
        }
    } else {
        int gid = (blockIdx.x - 2048) * 256 + threadIdx.x;
        int lane  = gid & 31;
        int mt    = (gid >> 5) & 15;
        int kc    = (gid >> 9) & 31;
        int btile = gid >> 14;
        int row = btile * 256 + mt * 16 + (lane >> 2);
        int k0  = kc * 16 + (lane & 3) * 2;
        float2 p00 = *(const float2*)&t[(size_t)row * 512 + k0];
        float2 p10 = *(const float2*)&t[(size_t)(row + 8) * 512 + k0];
        float2 p01 = *(const float2*)&t[(size_t)row * 512 + k0 + 8];
        float2 p11 = *(const float2*)&t[(size_t)(row + 8) * 512 + k0 + 8];
        *(uint4*)&g_T[(size_t)gid * 4] =
            make_uint4(packh2(p00.x, p00.y), packh2(p10.x, p10.y),
                       packh2(p01.x, p01.y), packh2(p11.x, p11.y));
    }
}

// ---------------- GEMM + f-dot epilogue ----------------
// A stages: 4 x 16KB (K32 each... stage s covers kc16 = 2s, 2s+1). B: direct LDG.
static constexpr uint32_t STAGE_SZ  = 16384;
static constexpr uint32_t SMEM_GEMM = 4 * STAGE_SZ;   // 64KB (>= 33.8KB f buffer)

__global__ __launch_bounds__(256, 1) void gemm_kernel(const float* __restrict__ f_feat) {
    extern __shared__ __align__(16) unsigned char smem_dyn[];
    uint32_t* smem = (uint32_t*)smem_dyn;
    int tid = threadIdx.x;
    int lane = tid & 31, warp = tid >> 5;
    int mw = warp & 3, nw = warp >> 2;
    int btile = blockIdx.x, jt = blockIdx.y, c = blockIdx.z;

    const char* gA = (const char*)g_T + (size_t)btile * 32 * 8192;
    const uint2* __restrict__ gBv = (const uint2*)g_W
        + (size_t)((c * 4 + jt) * 32) * 512 + nw * 256 + lane;   // (kc,nt,lane) -> kc*512 + nt*32

    uint32_t sbase = (uint32_t)__cvta_generic_to_shared(smem);

    // prime 3 A stages (16KB each = 64B/thread)
#pragma unroll
    for (int s = 0; s < 3; s++) {
        uint32_t d = sbase + s * STAGE_SZ;
#pragma unroll
        for (int q = 0; q < 4; q++)
            cp16(d + q * 4096 + tid * 16, gA + (size_t)s * STAGE_SZ + q * 4096 + tid * 16);
        cp_commit();
    }

    float acc[4][8][4];
#pragma unroll
    for (int mt = 0; mt < 4; mt++)
#pragma unroll
        for (int nt = 0; nt < 8; nt++)
#pragma unroll
            for (int q = 0; q < 4; q++) acc[mt][nt][q] = 0.f;

    // B register prefetch: ping-pong buffers, one k16-step ahead
    uint2 breg[2][8];
#pragma unroll
    for (int nt = 0; nt < 8; nt++) breg[0][nt] = gBv[(size_t)0 * 512 + nt * 32];

    for (int it = 0; it < 16; it++) {
        cp_wait2();
        __syncthreads();
        int s = it & 3;
        const uint32_t* sA = smem + s * (STAGE_SZ / 4);

#pragma unroll
        for (int sub = 0; sub < 2; sub++) {
            int p = it * 2 + sub;
            int pn = (p + 1 < 32) ? p + 1 : 31;      // clamp: harmless reload at end
            int cur = p & 1, nxt = cur ^ 1;
#pragma unroll
            for (int nt = 0; nt < 8; nt++)
                breg[nxt][nt] = gBv[(size_t)pn * 512 + nt * 32];

            const uint32_t* pA = sA + sub * 2048;
#pragma unroll
            for (int mt = 0; mt < 4; mt++) {
                uint4 aa = *(const uint4*)&pA[((mw * 4 + mt) * 32 + lane) * 4];
                uint32_t afr[4] = {aa.x, aa.y, aa.z, aa.w};
#pragma unroll
                for (int nt = 0; nt < 8; nt++)
                    mma_f16(acc[mt][nt], afr, (const uint32_t*)&breg[cur][nt]);
            }
        }

        if (it < 13) {
            int kn = it + 3;
            uint32_t d = sbase + (kn & 3) * STAGE_SZ;
#pragma unroll
            for (int q = 0; q < 4; q++)
                cp16(d + q * 4096 + tid * 16, gA + (size_t)kn * STAGE_SZ + q * 4096 + tid * 16);
        }
        cp_commit();   // empty group when it >= 13 keeps wait arithmetic uniform
    }

    // ---------------- epilogue: partial[b,c] = sum_j P[b,j] * f[b,j] ----------------
    float* fs = (float*)smem;   // 64 rows x 132 floats = 33.8KB
    for (int p = 0; p < 4; p++) {
        __syncthreads();
        for (int i = tid; i < 64 * 32; i += 256) {
            int row = i >> 5, cg = i & 31;
            float4 v = *(const float4*)&f_feat[(size_t)(btile * 256 + p * 64 + row) * 512 + jt * 128 + cg * 4];
            *(float4*)&fs[row * 132 + cg * 4] = v;
        }
        __syncthreads();
        if (mw == p) {
#pragma unroll
            for (int mt = 0; mt < 4; mt++) {
#pragma unroll
                for (int h = 0; h < 2; h++) {
                    int fl = mt * 16 + (lane >> 2) + 8 * h;
                    float sum = 0.f;
#pragma unroll
                    for (int nt = 0; nt < 8; nt++) {
                        float2 fv = *(const float2*)&fs[fl * 132 + nw * 64 + nt * 8 + 2 * (lane & 3)];
                        sum = fmaf(acc[mt][nt][h * 2], fv.x, sum);
                        sum = fmaf(acc[mt][nt][h * 2 + 1], fv.y, sum);
                    }
                    sum += __shfl_xor_sync(0xffffffffu, sum, 1);
                    sum += __shfl_xor_sync(0xffffffffu, sum, 2);
                    if ((lane & 3) == 0) {
                        int bb = btile * 256 + p * 64 + fl;
                        g_partial[(size_t)(jt * 2 + nw) * 131072 + (size_t)bb * 64 + c] = sum;
                    }
                }
            }
        }
    }
}

// ---------------- MLP: sum 8 slices + bias + relu + 64->32->1 ----------------
__global__ void mlp_kernel(const float* __restrict__ b_proj, const float* __restrict__ W1,
                           const float* __restrict__ b1, const float* __restrict__ W2,
                           const float* __restrict__ b2, float* __restrict__ out) {
    __shared__ float sW1[2048], sb1[32], sW2[32], sbp[64];
    int tid = threadIdx.x;
    for (int i = tid; i < 2048; i += 32) sW1[i] = W1[i];
    if (tid < 32) { sb1[tid] = b1[tid]; sW2[tid] = W2[tid]; }
    for (int i = tid; i < 64; i += 32) sbp[i] = b_proj[i];
    __syncthreads();

    int b = blockIdx.x * 32 + tid;
    float h[64];
#pragma unroll
    for (int cg = 0; cg < 16; cg++) {
        float4 v = *(const float4*)&g_partial[(size_t)b * 64 + cg * 4];
#pragma unroll
        for (int s = 1; s < 8; s++) {
            float4 p = *(const float4*)&g_partial[(size_t)s * 131072 + (size_t)b * 64 + cg * 4];
            v.x += p.x; v.y += p.y; v.z += p.z; v.w += p.w;
        }
        h[cg * 4 + 0] = fmaxf(v.x + sbp[cg * 4 + 0], 0.f);
        h[cg * 4 + 1] = fmaxf(v.y + sbp[cg * 4 + 1], 0.f);
        h[cg * 4 + 2] = fmaxf(v.z + sbp[cg * 4 + 2], 0.f);
        h[cg * 4 + 3] = fmaxf(v.w + sbp[cg * 4 + 3], 0.f);
    }
    float logit = b2[0];
#pragma unroll
    for (int k = 0; k < 32; k++) {
        float a = sb1[k];
#pragma unroll
        for (int cc = 0; cc < 64; cc++)
            a = fmaf(h[cc], sW1[k * 64 + cc], a);
        logit = fmaf(fmaxf(a, 0.f), sW2[k], logit);
    }
    out[b] = logit;
}

// ---------------- launcher ----------------
extern "C" void kernel_launch(void* const* d_in, const int* in_sizes, int n_in,
                              void* d_out, int out_size) {
    const float* t_feat = (const float*)d_in[0];
    const float* f_feat = (const float*)d_in[1];
    const float* W_proj = (const float*)d_in[2];
    const float* b_proj = (const float*)d_in[3];
    const float* W1     = (const float*)d_in[4];
    const float* b1     = (const float*)d_in[5];
    const float* W2     = (const float*)d_in[6];
    const float* b2     = (const float*)d_in[7];
    float* out = (float*)d_out;

    cudaFuncSetAttribute(gemm_kernel, cudaFuncAttributeMaxDynamicSharedMemorySize, SMEM_GEMM);

    conv_kernel<<<2560, 256>>>(t_feat, W_proj);
    dim3 grid(8, 4, 64);   // ONE launch: 2048 CTAs = 13.8 waves
    gemm_kernel<<<grid, 256, SMEM_GEMM>>>(f_feat);
    mlp_kernel<<<64, 32>>>(b_proj, W1, b1, W2, b2, out);
}

// round 10
// speedup vs baseline: 1.9546x; 1.1627x over previous
#include <cuda_runtime.h>
#include <cuda_fp16.h>
#include <cstdint>
#include <cstddef>

// ============================================================================
// proj[b,c] = sum_{i,j} t[b,i] * W[c, i*512+j] * f[b,j]   (B=2048, F=512, C=64)
// out = relu(relu(proj + bp) @ W1^T + b1) @ W2^T + b2
//
// fp16 mma.sync.m16n8k16. R8 profile: issue 16.8%, occ 12.4% -> latency-bound
// at 2 warps/SMSP. This round: CTA 128x128, 8 warps of 64x32, 2 CTAs/SM
// (4 warps/SMSP), B operand direct-LDG from L2 (fragment-ordered gmem),
// A via 4-stage cp.async (8KB/stage).
// ============================================================================

// g_T [btile128(8)... stored as][bt8][kc16(32)][mt(16)][lane(32)][4 u32] (2 MB)
// g_W [c(64)][jt(4)][kc16(32)][nt(16)][lane(32)][2 u32]                  (33.5 MB)
__device__ uint32_t g_T[8 * 32 * 16 * 32 * 4];
__device__ uint32_t g_W[64 * 4 * 32 * 16 * 32 * 2];
__device__ float    g_partial[16 * 2048 * 64];

// ---------------- helpers ----------------
__device__ __forceinline__ uint32_t packh2(float lo, float hi) {
    __half2 h = __floats2half2_rn(lo, hi);
    return *(uint32_t*)&h;
}
__device__ __forceinline__ void cp16(uint32_t dst_smem, const void* src) {
    asm volatile("cp.async.cg.shared.global [%0], [%1], 16;" :: "r"(dst_smem), "l"(src));
}
__device__ __forceinline__ void cp_commit() {
    asm volatile("cp.async.commit_group;" ::: "memory");
}
__device__ __forceinline__ void cp_wait2() {
    asm volatile("cp.async.wait_group 2;" ::: "memory");
}
__device__ __forceinline__ void mma_f16(float* d, const uint32_t* a, const uint32_t* b) {
    asm volatile(
        "mma.sync.aligned.m16n8k16.row.col.f32.f16.f16.f32 "
        "{%0,%1,%2,%3},{%4,%5,%6,%7},{%8,%9},{%0,%1,%2,%3};"
        : "+f"(d[0]), "+f"(d[1]), "+f"(d[2]), "+f"(d[3])
        : "r"(a[0]), "r"(a[1]), "r"(a[2]), "r"(a[3]), "r"(b[0]), "r"(b[1]));
}

// ---------------- conv (unchanged: fragment-order fp16) ----------------
__global__ void conv_kernel(const float* __restrict__ t, const float* __restrict__ W) {
    if (blockIdx.x < 2048) {
        __shared__ float ws[64 * 132];
        int b = blockIdx.x;
        int c = b >> 5, jt = (b >> 3) & 3, ktile = b & 7;
        int tid = threadIdx.x, lane = tid & 31, warp = tid >> 5;

        const float* src = W + (size_t)c * 262144 + (size_t)(ktile * 64) * 512 + jt * 128;
#pragma unroll
        for (int r = 0; r < 8; r++) {
            int k = r * 8 + warp;
            float4 v = *(const float4*)&src[(size_t)k * 512 + lane * 4];
            float* d = &ws[k * 132 + lane * 4];
            d[0] = v.x; d[1] = v.y; d[2] = v.z; d[3] = v.w;
        }
        __syncthreads();

#pragma unroll
        for (int i = 0; i < 8; i++) {
            int p = warp * 8 + i;
            int q = p >> 4, nt = p & 15;
            int k0 = q * 16 + (lane & 3) * 2;
            int n  = nt * 8 + (lane >> 2);
            uint32_t v0 = packh2(ws[k0 * 132 + n],       ws[(k0 + 1) * 132 + n]);
            uint32_t v1 = packh2(ws[(k0 + 8) * 132 + n], ws[(k0 + 9) * 132 + n]);
            size_t base = ((size_t)((c * 4 + jt) * 32 + ktile * 4 + q) * 16 + nt) * 64 + lane * 2;
            *(uint2*)&g_W[base] = make_uint2(v0, v1);
        }
    } else {
        int gid = (blockIdx.x - 2048) * 256 + threadIdx.x;
        int lane  = gid & 31;
        int mt    = (gid >> 5) & 15;
        int kc    = (gid >> 9) & 31;
        int btile = gid >> 14;
        int row = btile * 256 + mt * 16 + (lane >> 2);
        int k0  = kc * 16 + (lane & 3) * 2;
        float2 p00 = *(const float2*)&t[(size_t)row * 512 + k0];
        float2 p10 = *(const float2*)&t[(size_t)(row + 8) * 512 + k0];
        float2 p01 = *(const float2*)&t[(size_t)row * 512 + k0 + 8];
        float2 p11 = *(const float2*)&t[(size_t)(row + 8) * 512 + k0 + 8];
        *(uint4*)&g_T[(size_t)gid * 4] =
            make_uint4(packh2(p00.x, p00.y), packh2(p10.x, p10.y),
                       packh2(p01.x, p01.y), packh2(p11.x, p11.y));
    }
}

// ---------------- GEMM + f-dot epilogue ----------------
// CTA 128(m) x 128(n); 8 warps: mw=warp&1 (64 rows), nw=warp>>1 (32 cols).
// A stages: 4 x 8KB (stage = K32 = 2 kc16-slabs of 4KB). B: direct LDG.64.
static constexpr uint32_t STAGE_SZ  = 8192;
static constexpr uint32_t SMEM_GEMM = 33792;   // max(4 stages 32KB, f buf 64x132x4)

__global__ __launch_bounds__(256, 2) void gemm_kernel(const float* __restrict__ f_feat) {
    extern __shared__ __align__(16) unsigned char smem_dyn[];
    uint32_t* smem = (uint32_t*)smem_dyn;
    int tid = threadIdx.x;
    int lane = tid & 31, warp = tid >> 5;
    int mw = warp & 1, nw = warp >> 1;
    int btile = blockIdx.x, jt = blockIdx.y, c = blockIdx.z;

    // A source: old 256-row block (btile>>1), rows (btile&1)*128..+128 = mt 8..15 half
    const char* gA = (const char*)g_T + (size_t)(btile >> 1) * 32 * 8192 + (btile & 1) * 4096;
    // B fragments: uint2 index [(c*4+jt)*32 + kc]*512 + nt*32 + lane
    const uint2* __restrict__ gBv = (const uint2*)g_W
        + (size_t)((c * 4 + jt) * 32) * 512 + (nw * 4) * 32 + lane;

    uint32_t sbase = (uint32_t)__cvta_generic_to_shared(smem);

    // prime 3 stages: per stage two 4KB slabs (kc = 2s, 2s+1), 16B/thread each
#pragma unroll
    for (int s = 0; s < 3; s++) {
        uint32_t d = sbase + s * STAGE_SZ;
        cp16(d + tid * 16,        gA + (size_t)(2 * s) * 8192 + tid * 16);
        cp16(d + 4096 + tid * 16, gA + (size_t)(2 * s + 1) * 8192 + tid * 16);
        cp_commit();
    }

    float acc[4][4][4];
#pragma unroll
    for (int mt = 0; mt < 4; mt++)
#pragma unroll
        for (int nt = 0; nt < 4; nt++)
#pragma unroll
            for (int q = 0; q < 4; q++) acc[mt][nt][q] = 0.f;

    // B ping-pong prefetch, one k16-step ahead
    uint2 breg[2][4];
#pragma unroll
    for (int nt = 0; nt < 4; nt++) breg[0][nt] = gBv[nt * 32];

    for (int it = 0; it < 16; it++) {
        cp_wait2();
        __syncthreads();
        int s = it & 3;
        const uint32_t* sA = smem + s * (STAGE_SZ / 4);

#pragma unroll
        for (int sub = 0; sub < 2; sub++) {
            int p = it * 2 + sub;
            int pn = (p + 1 < 32) ? p + 1 : 31;
            int cur = p & 1, nxt = cur ^ 1;
#pragma unroll
            for (int nt = 0; nt < 4; nt++)
                breg[nxt][nt] = gBv[(size_t)pn * 512 + nt * 32];

            const uint32_t* pA = sA + sub * 1024;
#pragma unroll
            for (int mt = 0; mt < 4; mt++) {
                uint4 aa = *(const uint4*)&pA[((mw * 4 + mt) * 32 + lane) * 4];
                uint32_t afr[4] = {aa.x, aa.y, aa.z, aa.w};
#pragma unroll
                for (int nt = 0; nt < 4; nt++)
                    mma_f16(acc[mt][nt], afr, (const uint32_t*)&breg[cur][nt]);
            }
        }

        if (it < 13) {
            int kn = it + 3;
            uint32_t d = sbase + (kn & 3) * STAGE_SZ;
            cp16(d + tid * 16,        gA + (size_t)(2 * kn) * 8192 + tid * 16);
            cp16(d + 4096 + tid * 16, gA + (size_t)(2 * kn + 1) * 8192 + tid * 16);
        }
        cp_commit();   // empty group when it >= 13 keeps wait arithmetic uniform
    }

    // ---------------- epilogue: partial[b,c] = sum_j P[b,j] * f[b,j] ----------------
    float* fs = (float*)smem;   // 64 rows x 132 floats
    for (int p = 0; p < 2; p++) {
        __syncthreads();
        for (int i = tid; i < 64 * 32; i += 256) {
            int row = i >> 5, cg = i & 31;
            float4 v = *(const float4*)&f_feat[(size_t)(btile * 128 + p * 64 + row) * 512 + jt * 128 + cg * 4];
            *(float4*)&fs[row * 132 + cg * 4] = v;
        }
        __syncthreads();
        if (mw == p) {
#pragma unroll
            for (int mt = 0; mt < 4; mt++) {
#pragma unroll
                for (int h = 0; h < 2; h++) {
                    int fl = mt * 16 + (lane >> 2) + 8 * h;   // local row 0..63
                    float sum = 0.f;
#pragma unroll
                    for (int nt = 0; nt < 4; nt++) {
                        float2 fv = *(const float2*)&fs[fl * 132 + nw * 32 + nt * 8 + 2 * (lane & 3)];
                        sum = fmaf(acc[mt][nt][h * 2], fv.x, sum);
                        sum = fmaf(acc[mt][nt][h * 2 + 1], fv.y, sum);
                    }
                    sum += __shfl_xor_sync(0xffffffffu, sum, 1);
                    sum += __shfl_xor_sync(0xffffffffu, sum, 2);
                    if ((lane & 3) == 0) {
                        int bb = btile * 128 + p * 64 + fl;
                        g_partial[(size_t)(jt * 4 + nw) * 131072 + (size_t)bb * 64 + c] = sum;
                    }
                }
            }
        }
    }
}

// ---------------- MLP: sum 16 slices + bias + relu + 64->32->1 ----------------
__global__ void mlp_kernel(const float* __restrict__ b_proj, const float* __restrict__ W1,
                           const float* __restrict__ b1, const float* __restrict__ W2,
                           const float* __restrict__ b2, float* __restrict__ out) {
    __shared__ float sW1[2048], sb1[32], sW2[32], sbp[64];
    int tid = threadIdx.x;
    for (int i = tid; i < 2048; i += 32) sW1[i] = W1[i];
    if (tid < 32) { sb1[tid] = b1[tid]; sW2[tid] = W2[tid]; }
    for (int i = tid; i < 64; i += 32) sbp[i] = b_proj[i];
    __syncthreads();

    int b = blockIdx.x * 32 + tid;
    float h[64];
#pragma unroll
    for (int cg = 0; cg < 16; cg++) {
        float4 v = *(const float4*)&g_partial[(size_t)b * 64 + cg * 4];
#pragma unroll
        for (int s = 1; s < 16; s++) {
            float4 p = *(const float4*)&g_partial[(size_t)s * 131072 + (size_t)b * 64 + cg * 4];
            v.x += p.x; v.y += p.y; v.z += p.z; v.w += p.w;
        }
        h[cg * 4 + 0] = fmaxf(v.x + sbp[cg * 4 + 0], 0.f);
        h[cg * 4 + 1] = fmaxf(v.y + sbp[cg * 4 + 1], 0.f);
        h[cg * 4 + 2] = fmaxf(v.z + sbp[cg * 4 + 2], 0.f);
        h[cg * 4 + 3] = fmaxf(v.w + sbp[cg * 4 + 3], 0.f);
    }
    float logit = b2[0];
#pragma unroll
    for (int k = 0; k < 32; k++) {
        float a = sb1[k];
#pragma unroll
        for (int cc = 0; cc < 64; cc++)
            a = fmaf(h[cc], sW1[k * 64 + cc], a);
        logit = fmaf(fmaxf(a, 0.f), sW2[k], logit);
    }
    out[b] = logit;
}

// ---------------- launcher ----------------
extern "C" void kernel_launch(void* const* d_in, const int* in_sizes, int n_in,
                              void* d_out, int out_size) {
    const float* t_feat = (const float*)d_in[0];
    const float* f_feat = (const float*)d_in[1];
    const float* W_proj = (const float*)d_in[2];
    const float* b_proj = (const float*)d_in[3];
    const float* W1     = (const float*)d_in[4];
    const float* b1     = (const float*)d_in[5];
    const float* W2     = (const float*)d_in[6];
    const float* b2     = (const float*)d_in[7];
    float* out = (float*)d_out;

    cudaFuncSetAttribute(gemm_kernel, cudaFuncAttributeMaxDynamicSharedMemorySize, SMEM_GEMM);

    conv_kernel<<<2560, 256>>>(t_feat, W_proj);
    dim3 grid(16, 4, 64);   // 4096 CTAs, 2 CTAs/SM
    gemm_kernel<<<grid, 256, SMEM_GEMM>>>(f_feat);
    mlp_kernel<<<64, 32>>>(b_proj, W1, b1, W2, b2, out);
}